// round 12
// baseline (speedup 1.0000x reference)
#include <cuda_runtime.h>
#include <stdint.h>

#define NPART_MAX 100000
#define CUTOFF 0.9f
#define PREFAC 138.93544539709032f

#define NBINS 32
#define BIN_W_MAX 3125                       // ceil(100000/32)
#define K1_THREADS 256
#define K1_BLOCKS 1184
#define K1_WARPS (K1_THREADS / 32)           // 8
#define NWARPS_TOT (K1_BLOCKS * K1_WARPS)    // 9472
#define WCAP 160                             // per-(warp,bin) capacity: mean ~53, 15 sigma headroom
#define BLOCKS_PER_BIN 74
#define K2_BLOCKS (NBINS * BLOCKS_PER_BIN)   // 2368
#define WG_PER_BLOCK (NWARPS_TOT / BLOCKS_PER_BIN)  // 128 (exact)

// Particle tables (built by pack kernel)
__device__ float4 g_pos[NPART_MAX];          // {x, y, z, q*sqrt(PREFAC)}
__device__ float2 g_sig[NPART_MAX];          // {sigma, epsilon}

// Partitioned pair words: [bin][warp_gid][slot] -> (j << 12) | i_local
__device__ unsigned int g_binned[(size_t)NBINS * NWARPS_TOT * WCAP];
__device__ unsigned int g_wcounts[(size_t)NWARPS_TOT * NBINS];

// ---------------------------------------------------------------------------
__device__ __forceinline__ float pair_energy_direct(int i, int j,
                                                    float Lx, float Ly, float Lz,
                                                    float iLx, float iLy, float iLz,
                                                    float cut2)
{
    float4 a = g_pos[i];
    float4 b = g_pos[j];
    float dx = a.x - b.x;
    float dy = a.y - b.y;
    float dz = a.z - b.z;
    dx -= Lx * rintf(dx * iLx);
    dy -= Ly * rintf(dy * iLy);
    dz -= Lz * rintf(dz * iLz);
    float r2 = dx * dx + dy * dy + dz * dz;
    if (r2 < cut2 && (i / 3 != j / 3)) {
        float2 sa = g_sig[i];
        float2 sb = g_sig[j];
        float inv_r  = rsqrtf(r2);
        float inv_r2 = inv_r * inv_r;
        float e_coul = a.w * b.w * inv_r;
        float sig = 0.5f * (sa.x + sb.x);
        float eps = sqrtf(sa.y * sb.y);
        float sr2 = sig * sig * inv_r2;
        float sr6 = sr2 * sr2 * sr2;
        return e_coul + 4.0f * eps * (sr6 * sr6 - sr6);
    }
    return 0.0f;
}

// ---------------------------------------------------------------------------
__global__ void pack_kernel(const float* __restrict__ coords,
                            const float* __restrict__ charges,
                            const float* __restrict__ sigma,
                            const float* __restrict__ epsilon,
                            float* __restrict__ out,
                            int n)
{
    int i = blockIdx.x * blockDim.x + threadIdx.x;
    if (i == 0) out[0] = 0.0f;               // d_out poisoned to 0xAA; zero it
    if (i < n) {
        float x = coords[3 * i + 0];
        float y = coords[3 * i + 1];
        float z = coords[3 * i + 2];
        g_pos[i] = make_float4(x, y, z, charges[i] * sqrtf(PREFAC));
        g_sig[i] = make_float2(sigma[i], epsilon[i]);
    }
}

// ---------------------------------------------------------------------------
// K1: partition pairs by i-bin into warp-private global regions. Atomic-free:
// __match_any ranking + per-warp smem running counters (LDS/STS + syncwarp).
// Overflow safety: a pair that would exceed WCAP (prob ~0) is computed
// directly here instead of being dropped -> correctness is unconditional.
__global__ void __launch_bounds__(K1_THREADS)
partition_kernel(const int2* __restrict__ pairs, int npairs, int bin_w,
                 const float* __restrict__ box, float* __restrict__ out)
{
    __shared__ int s_cnt[K1_WARPS][NBINS + 1];   // +1 slot absorbs invalid lanes
    int lane = threadIdx.x & 31;
    int w    = threadIdx.x >> 5;
    int wgid = blockIdx.x * K1_WARPS + w;

    if (lane <= NBINS) s_cnt[w][lane] = 0;
    __syncwarp();

    int ppw   = (npairs + NWARPS_TOT - 1) / NWARPS_TOT;  // pairs per warp
    int start = wgid * ppw;
    int end   = start + ppw;
    if (end > npairs) end = npairs;

    const unsigned lmask_lt = (lane == 0) ? 0u : (0xffffffffu >> (32 - lane));
    float ovf_acc = 0.0f;
    bool any_ovf = false;

    for (int base_i = start; base_i < end; base_i += 32) {
        int idx    = base_i + lane;
        bool valid = idx < end;
        int2 p = valid ? __ldcs(&pairs[idx]) : make_int2(0, 0);
        int bin = valid ? (p.x / bin_w) : NBINS;
        unsigned word = ((unsigned)p.y << 12) | (unsigned)(p.x - bin * bin_w);

        unsigned m = __match_any_sync(0xffffffffu, bin);
        int rank   = __popc(m & lmask_lt);
        int cbase  = s_cnt[w][bin];
        __syncwarp();
        if (rank == 0) s_cnt[w][bin] = cbase + __popc(m);  // group leader
        __syncwarp();

        int slot = cbase + rank;
        if (valid && bin < NBINS) {
            if (slot < WCAP) {
                g_binned[((size_t)bin * NWARPS_TOT + wgid) * WCAP + slot] = word;
            } else {
                // never expected; compute on the spot for unconditional correctness
                any_ovf = true;
            }
        }
        if (__any_sync(0xffffffffu, any_ovf)) {
            if (any_ovf) {
                float Lx = __ldg(&box[0]), Ly = __ldg(&box[4]), Lz = __ldg(&box[8]);
                ovf_acc += pair_energy_direct(p.x, p.y, Lx, Ly, Lz,
                                              __frcp_rn(Lx), __frcp_rn(Ly), __frcp_rn(Lz),
                                              CUTOFF * CUTOFF);
                any_ovf = false;
            }
        }
    }

    if (lane < NBINS) {
        int c = s_cnt[w][lane];
        g_wcounts[(size_t)wgid * NBINS + lane] = (c > WCAP) ? WCAP : (unsigned)c;
    }

    // fold any overflow energy into the result (normally all zeros -> no atomic)
    #pragma unroll
    for (int off = 16; off > 0; off >>= 1)
        ovf_acc += __shfl_xor_sync(0xffffffffu, ovf_acc, off);
    if (lane == 0 && ovf_acc != 0.0f) atomicAdd(out, ovf_acc);
}

// ---------------------------------------------------------------------------
// K2: per-bin energy. i-side from smem slice (LDS), j-side LDG (the wf bound).
__global__ void __launch_bounds__(256)
energy2_kernel(const float* __restrict__ box, float* __restrict__ out,
               int n, int bin_w)
{
    __shared__ float4 s_pos[BIN_W_MAX];

    int bin   = blockIdx.x / BLOCKS_PER_BIN;
    int chunk = blockIdx.x % BLOCKS_PER_BIN;
    int ibase = bin * bin_w;

    int nslice = n - ibase;
    if (nslice > bin_w) nslice = bin_w;
    if (nslice < 0) nslice = 0;
    for (int t = threadIdx.x; t < nslice; t += 256)
        s_pos[t] = g_pos[ibase + t];
    __syncthreads();

    float Lx = __ldg(&box[0]), Ly = __ldg(&box[4]), Lz = __ldg(&box[8]);
    float iLx = __frcp_rn(Lx), iLy = __frcp_rn(Ly), iLz = __frcp_rn(Lz);
    const float cut2 = CUTOFF * CUTOFF;

    float acc = 0.0f;
    int lane = threadIdx.x & 31;
    int w    = threadIdx.x >> 5;
    int wg0  = chunk * WG_PER_BLOCK;

    for (int wi = w; wi < WG_PER_BLOCK; wi += 8) {
        int wg  = wg0 + wi;
        int cnt = (int)g_wcounts[(size_t)wg * NBINS + bin];
        const unsigned* src = &g_binned[((size_t)bin * NWARPS_TOT + wg) * WCAP];
        for (int s = lane; s < cnt; s += 32) {
            unsigned word = __ldcs(&src[s]);
            int il = (int)(word & 4095u);
            int j  = (int)(word >> 12);
            float4 a = s_pos[il];                 // smem gather
            float4 b = g_pos[j];                  // the remaining LDG wavefront

            float dx = a.x - b.x;
            float dy = a.y - b.y;
            float dz = a.z - b.z;
            dx -= Lx * rintf(dx * iLx);
            dy -= Ly * rintf(dy * iLy);
            dz -= Lz * rintf(dz * iLz);
            float r2 = dx * dx + dy * dy + dz * dz;

            int i = ibase + il;
            if (r2 < cut2 && (i / 3 != j / 3)) {  // ~0.3% taken
                float2 sa = g_sig[i];
                float2 sb = g_sig[j];
                float inv_r  = rsqrtf(r2);
                float inv_r2 = inv_r * inv_r;
                float e_coul = a.w * b.w * inv_r;
                float sig = 0.5f * (sa.x + sb.x);
                float eps = sqrtf(sa.y * sb.y);
                float sr2 = sig * sig * inv_r2;
                float sr6 = sr2 * sr2 * sr2;
                acc += e_coul + 4.0f * eps * (sr6 * sr6 - sr6);
            }
        }
    }

    // warp reduce
    #pragma unroll
    for (int off = 16; off > 0; off >>= 1)
        acc += __shfl_xor_sync(0xFFFFFFFFu, acc, off);

    __shared__ float warp_sums[8];
    if (lane == 0) warp_sums[w] = acc;
    __syncthreads();
    if (w == 0) {
        float v = (lane < 8) ? warp_sums[lane] : 0.0f;
        #pragma unroll
        for (int off = 4; off > 0; off >>= 1)
            v += __shfl_xor_sync(0xFFFFFFFFu, v, off);
        if (lane == 0) atomicAdd(out, v);
    }
}

// ---------------------------------------------------------------------------
extern "C" void kernel_launch(void* const* d_in, const int* in_sizes, int n_in,
                              void* d_out, int out_size)
{
    const float* coords  = (const float*)d_in[0];
    const float* box     = (const float*)d_in[1];
    const float* charges = (const float*)d_in[2];
    const float* sigma   = (const float*)d_in[3];
    const float* epsilon = (const float*)d_in[4];
    const int*   pairs   = (const int*)d_in[5];

    int n      = in_sizes[2];
    int npairs = in_sizes[5] / 2;
    int bin_w  = (n + NBINS - 1) / NBINS;     // 3125 for n=100000

    float* out = (float*)d_out;

    pack_kernel<<<(n + 255) / 256, 256>>>(coords, charges, sigma, epsilon, out, n);
    partition_kernel<<<K1_BLOCKS, K1_THREADS>>>((const int2*)pairs, npairs, bin_w, box, out);
    energy2_kernel<<<K2_BLOCKS, 256>>>(box, out, n, bin_w);
}